// round 14
// baseline (speedup 1.0000x reference)
#include <cuda_runtime.h>
#include <cuda_bf16.h>
#include <cuda_fp16.h>
#include <stdint.h>
#include <math.h>

#define NB   8
#define CIN  256
#define COUT 256
#define HW   4096            // 64*64
#define CK   2304            // CIN*9
#define KC   16              // ck per chunk
#define NCH  144             // 2304/16
#define WSTR 48              // SMEM row stride (bytes): 16 fp16 + pad

// ---------------- device scratch ----------------
__device__ float          g_offset[NB * 18 * HW];
// pre-tiled weights: [chunk 144][o 256][ck 16] fp16
__device__ unsigned short g_w2h[NCH * COUT * KC];

// ---------------- SMEM layout (bytes) ----------------
#define S_TABA 0                       // int2[1152]  (9 taps x 128 p)
#define S_TABW 9216                    // float4[1152]
#define S_W0   27648                   // buf stride 12288 (256 rows x 48B)
#define S_V0   52224                   // buf stride 6144  (V fp16, 128 rows)
#define S_H0   64512                   // halo: buf stride 12288 (3ch x 16row x 64col f32)
#define S_TOTAL 89088

// ---------------------------------------------------------------------------
// k_prep: round w2 (fp32 [o][ck]) to fp16, tiled [chunk][o][ck%16]
// ---------------------------------------------------------------------------
__global__ void k_prep(const float* __restrict__ w2) {
    int i = blockIdx.x * 512 + threadIdx.x;     // 1152*512 = 589824 exact
    int o  = i / CK;
    int ck = i - o * CK;
    float v = w2[i];
    unsigned short hb;
    asm("cvt.rn.f16.f32 %0, %1;" : "=h"(hb) : "f"(v));
    int dst = ((ck >> 4) * COUT + o) * KC + (ck & 15);
    g_w2h[dst] = hb;
}

// ---------------------------------------------------------------------------
// k_off: offset-predicting 3x3 conv (18 out channels), pad=1 stride=1
// ---------------------------------------------------------------------------
__global__ __launch_bounds__(256) void k_off(const float* __restrict__ x,
                                             const float* __restrict__ w1) {
    __shared__ float xs[8][4][66];
    __shared__ float ws[8][9][18];

    int n  = blockIdx.x >> 5;
    int y0 = (blockIdx.x & 31) * 2;
    int tid = threadIdx.x;
    int p    = tid >> 1;
    int half = tid & 1;
    int r   = p >> 6;
    int col = p & 63;
    int o0  = half * 9;

    float acc[9];
#pragma unroll
    for (int j = 0; j < 9; j++) acc[j] = 0.f;

    for (int cb = 0; cb < CIN; cb += 8) {
        for (int l = tid; l < 8 * 4 * 66; l += 256) {
            int c  = l / 264;
            int rem = l - c * 264;
            int y  = rem / 66;
            int xc = rem - y * 66;
            int gy = y0 - 1 + y;
            int gx = xc - 1;
            float v = 0.f;
            if ((unsigned)gy < 64u && (unsigned)gx < 64u)
                v = x[((n * CIN + cb + c) * 64 + gy) * 64 + gx];
            xs[c][y][xc] = v;
        }
        for (int l = tid; l < 8 * 9 * 18; l += 256) {
            int o = l % 18;
            int k = (l / 18) % 9;
            int c = l / 162;
            ws[c][k][o] = w1[(o * CIN + cb + c) * 9 + k];
        }
        __syncthreads();

#pragma unroll
        for (int c = 0; c < 8; c++) {
            float xv[9];
#pragma unroll
            for (int ky = 0; ky < 3; ky++)
#pragma unroll
                for (int kx = 0; kx < 3; kx++)
                    xv[ky * 3 + kx] = xs[c][r + ky][col + kx];
#pragma unroll
            for (int k = 0; k < 9; k++) {
                float v = xv[k];
#pragma unroll
                for (int j = 0; j < 9; j++)
                    acc[j] += ws[c][k][o0 + j] * v;
            }
        }
        __syncthreads();
    }

    int hw = (y0 + r) * 64 + col;
#pragma unroll
    for (int j = 0; j < 9; j++)
        g_offset[(n * 18 + o0 + j) * HW + hw] = acc[j];
}

// ---------------------------------------------------------------------------
// HMMA wrapper
// ---------------------------------------------------------------------------
__device__ __forceinline__ void mma16816f(float* c, const uint32_t* a,
                                          const uint32_t* b) {
    asm volatile(
        "mma.sync.aligned.m16n8k16.row.col.f32.f16.f16.f32 "
        "{%0,%1,%2,%3}, {%4,%5,%6,%7}, {%8,%9}, {%0,%1,%2,%3};"
        : "+f"(c[0]), "+f"(c[1]), "+f"(c[2]), "+f"(c[3])
        : "r"(a[0]), "r"(a[1]), "r"(a[2]), "r"(a[3]), "r"(b[0]), "r"(b[1]));
}

// ---------------------------------------------------------------------------
// k_main: SMEM-halo gather -> single-pass fp16 mma.sync GEMM
// Block: 512 threads (16 warps, 4m x 4n), tile 256o x 128p, K-chunk 16.
// Per chunk: x row-halo (16 rows x 3 ch) staged coalesced into SMEM (double-
// buffered, prefetched during MMA); bilinear gather via LDS with LDG fallback.
// Grid: 8 n * 32 ptiles = 256 blocks.
// ---------------------------------------------------------------------------
__global__ __launch_bounds__(512, 1) void k_main(const float* __restrict__ x,
                                                 const float* __restrict__ b2,
                                                 float* __restrict__ out) {
    extern __shared__ __align__(16) char smem[];
    int tid = threadIdx.x;
    int wid = tid >> 5;
    int lane = tid & 31;
    int g  = lane >> 2;
    int t2 = lane & 3;

    int n     = blockIdx.x >> 5;
    int pbase = (blockIdx.x & 31) * 128;
    int row_lo = (pbase >> 6) - 6;          // halo rows [row_lo, row_lo+15]
    int lbase  = pbase - 384;               // row_lo * 64

    int o_base = (wid & 3) * 64;
    int p_base = (wid >> 2) * 32;
    int pg = tid & 127;          // gather position
    int jg = tid >> 7;           // gather ck-group (0..3), 4 ck each

    // ---- bilinear table: 9 taps x 128 positions ----
    for (int t = tid; t < 1152; t += 512) {
        int tap = t >> 7;
        int p   = t & 127;
        int hw  = pbase + p;
        int h   = hw >> 6;
        int w   = hw & 63;
        float dy = g_offset[(n * 18 + 2 * tap)     * HW + hw];
        float dx = g_offset[(n * 18 + 2 * tap + 1) * HW + hw];
        float py = (float)(h - 1 + tap / 3) + dy;
        float px = (float)(w - 1 + tap % 3) + dx;
        float fy = floorf(py), fx = floorf(px);
        float wy = py - fy, wx = px - fx;
        int y0 = (int)fy, x0 = (int)fx;
        float vy0 = ((unsigned)y0       < 64u) ? 1.f : 0.f;
        float vy1 = ((unsigned)(y0 + 1) < 64u) ? 1.f : 0.f;
        float vx0 = ((unsigned)x0       < 64u) ? 1.f : 0.f;
        float vx1 = ((unsigned)(x0 + 1) < 64u) ? 1.f : 0.f;
        float wy0 = (1.f - wy) * vy0, wy1 = wy * vy1;
        float wx0 = (1.f - wx) * vx0, wx1 = wx * vx1;
        int y0c = min(max(y0, 0), 63), y1c = min(max(y0 + 1, 0), 63);
        int x0c = min(max(x0, 0), 63), x1c = min(max(x0 + 1, 0), 63);
        int a00 = (y0c << 6) + x0c;
        int dxo = x1c - x0c;
        int dyo = (y1c - y0c) << 6;
        *(int2*)(smem + S_TABA + t * 8)    = make_int2(a00, dxo | (dyo << 16));
        *(float4*)(smem + S_TABW + t * 16) = make_float4(wy0 * wx0, wy0 * wx1,
                                                         wy1 * wx0, wy1 * wx1);
    }

    float acc[4][4][4];
#pragma unroll
    for (int mt = 0; mt < 4; mt++)
#pragma unroll
        for (int nt = 0; nt < 4; nt++)
#pragma unroll
            for (int j = 0; j < 4; j++) acc[mt][nt][j] = 0.f;

    const float* xn = x + ((size_t)n << 20);
    const uint4* wsrch = (const uint4*)(g_w2h);
    int wrow = tid >> 1;
    int wseg = tid & 1;

    __syncthreads();

    uint4 hreg[2];
    uint4 wregh;

    // ---- prologue: load halo + W for chunk 0, store to buf 0 ----
    {
#pragma unroll
        for (int it = 0; it < 2; it++) {
            int idx = tid + it * 512;
            if (idx < 768) {
                int ch = idx >> 8;
                int rr = (idx >> 4) & 15;
                int ss = idx & 15;
                int cc2 = min(ch, 255);
                int r_abs = min(max(row_lo + rr, 0), 63);
                hreg[it] = *(const uint4*)(xn + (cc2 << 12) + r_abs * 64 + ss * 4);
            }
        }
        wregh = wsrch[(0 * COUT + wrow) * 2 + wseg];
#pragma unroll
        for (int it = 0; it < 2; it++) {
            int idx = tid + it * 512;
            if (idx < 768)
                *(uint4*)(smem + S_H0 + (idx << 4)) = hreg[it];
        }
        *(uint4*)(smem + S_W0 + wrow * WSTR + wseg * 16) = wregh;
    }
    __syncthreads();

    for (int cb = 0; cb < NCH; cb++) {
        int cur = cb & 1;
        int nxt = cur ^ 1;

        // ---- gather from halo (LDS) + combine -> store V cur ----
        {
            int c_lo = (cb * 16) / 9;
            int ck0 = cb * KC + jg * 4;
            int c = ck0 / 9, tap = ck0 - c * 9;
            unsigned vb2[2];
#pragma unroll
            for (int kk = 0; kk < 4; kk++) {
                int t = (tap << 7) + pg;
                int2   ia = *(const int2*)(smem + S_TABA + t * 8);
                float4 wt = *(const float4*)(smem + S_TABW + t * 16);
                int a00 = ia.x, dxo = ia.y & 0xFFFF, dyo = ia.y >> 16;
                int local = a00 - lbase;
                float v00, v01, v10, v11;
                if (((unsigned)local < 1024u) && ((unsigned)(local + dyo) < 1024u)) {
                    const float* hb = (const float*)(smem + S_H0 + cur * 12288
                                                     + ((c - c_lo) << 12));
                    v00 = hb[local];
                    v01 = hb[local + dxo];
                    v10 = hb[local + dyo];
                    v11 = hb[local + dyo + dxo];
                } else {
                    const float* xp = xn + (c << 12);
                    v00 = __ldg(xp + a00);
                    v01 = __ldg(xp + a00 + dxo);
                    v10 = __ldg(xp + a00 + dyo);
                    v11 = __ldg(xp + a00 + dyo + dxo);
                }
                float v = wt.x * v00 + wt.y * v01 + wt.z * v10 + wt.w * v11;
                unsigned short hv;
                asm("cvt.rn.f16.f32 %0, %1;" : "=h"(hv) : "f"(v));
                if (kk & 1) vb2[kk >> 1] |= ((unsigned)hv) << 16;
                else        vb2[kk >> 1]  = hv;
                if (++tap == 9) { tap = 0; c++; }
            }
            *(uint2*)(smem + S_V0 + cur * 6144 + pg * WSTR + jg * 8)
                = make_uint2(vb2[0], vb2[1]);
        }

        // ---- issue prefetch LDGs for chunk cb+1 (fly under the MMAs) ----
        if (cb + 1 < NCH) {
            int ci = ((cb + 1) * 16) / 9;
#pragma unroll
            for (int it = 0; it < 2; it++) {
                int idx = tid + it * 512;
                if (idx < 768) {
                    int ch = idx >> 8;
                    int rr = (idx >> 4) & 15;
                    int ss = idx & 15;
                    int cc2 = min(ci + ch, 255);
                    int r_abs = min(max(row_lo + rr, 0), 63);
                    hreg[it] = *(const uint4*)(xn + (cc2 << 12) + r_abs * 64 + ss * 4);
                }
            }
            wregh = wsrch[((cb + 1) * COUT + wrow) * 2 + wseg];
        }
        __syncthreads();   // V stores visible to MMA

        // ---- MMA on buf cur: single fp16 pass ----
        {
            const char* wh = smem + S_W0 + cur * 12288;
            const char* vv = smem + S_V0 + cur * 6144;

            uint32_t b[4][2];
#pragma unroll
            for (int nt = 0; nt < 4; nt++) {
                const char* rp = vv + (p_base + nt * 8 + g) * WSTR + t2 * 4;
                b[nt][0] = *(const uint32_t*)(rp);
                b[nt][1] = *(const uint32_t*)(rp + 16);
            }
#pragma unroll
            for (int mt = 0; mt < 4; mt++) {
                int ro = (o_base + mt * 16 + g) * WSTR + t2 * 4;
                uint32_t ah[4];
                ah[0] = *(const uint32_t*)(wh + ro);
                ah[1] = *(const uint32_t*)(wh + ro + 8 * WSTR);
                ah[2] = *(const uint32_t*)(wh + ro + 16);
                ah[3] = *(const uint32_t*)(wh + ro + 8 * WSTR + 16);
#pragma unroll
                for (int nt = 0; nt < 4; nt++)
                    mma16816f(acc[mt][nt], ah, b[nt]);
            }
        }

        // ---- store prefetched halo + W into buf nxt ----
        if (cb + 1 < NCH) {
#pragma unroll
            for (int it = 0; it < 2; it++) {
                int idx = tid + it * 512;
                if (idx < 768)
                    *(uint4*)(smem + S_H0 + nxt * 12288 + (idx << 4)) = hreg[it];
            }
            *(uint4*)(smem + S_W0 + nxt * 12288 + wrow * WSTR + wseg * 16) = wregh;
        }
        __syncthreads();   // halo/W nxt visible to next iteration's gather
    }

    // ---- epilogue: bias + float2 stores ----
#pragma unroll
    for (int mt = 0; mt < 4; mt++) {
        int o0 = o_base + mt * 16 + g;
        float bias0 = b2[o0];
        float bias1 = b2[o0 + 8];
        float* row0 = out + (size_t)(n * COUT + o0) * HW + pbase;
        float* row1 = row0 + 8 * HW;
#pragma unroll
        for (int nt = 0; nt < 4; nt++) {
            int p = p_base + nt * 8 + t2 * 2;
            *(float2*)(row0 + p) = make_float2(acc[mt][nt][0] + bias0,
                                               acc[mt][nt][1] + bias0);
            *(float2*)(row1 + p) = make_float2(acc[mt][nt][2] + bias1,
                                               acc[mt][nt][3] + bias1);
        }
    }
}

// ---------------------------------------------------------------------------
extern "C" void kernel_launch(void* const* d_in, const int* in_sizes, int n_in,
                              void* d_out, int out_size) {
    const float* x  = (const float*)d_in[0];
    const float* w1 = (const float*)d_in[1];
    const float* w2 = (const float*)d_in[2];
    const float* b2 = (const float*)d_in[3];
    float* out = (float*)d_out;

    cudaFuncSetAttribute(k_main, cudaFuncAttributeMaxDynamicSharedMemorySize,
                         S_TOTAL);

    k_prep<<<1152, 512>>>(w2);
    k_off<<<NB * 32, 256>>>(x, w1);
    k_main<<<NB * 32, 512, S_TOTAL>>>(x, b2, out);
}

// round 15
// speedup vs baseline: 1.3864x; 1.3864x over previous
#include <cuda_runtime.h>
#include <cuda_bf16.h>
#include <cuda_fp16.h>
#include <stdint.h>
#include <math.h>

#define NB   8
#define CIN  256
#define COUT 256
#define HW   4096            // 64*64
#define CK   2304            // CIN*9
#define KC   16              // ck per chunk
#define NCH  144             // 2304/16
#define WSTR 48              // SMEM row stride (bytes): 16 fp16 + pad

// ---------------- device scratch ----------------
__device__ float          g_offset[NB * 18 * HW];
// pre-tiled weights: [chunk 144][o 256][ck 16] fp16
__device__ unsigned short g_w2h[NCH * COUT * KC];

// ---------------- SMEM layout for k_main (bytes) ----------------
#define S_TABA 0                       // int2[1152]  (9 taps x 128 p)
#define S_TABW 9216                    // float4[1152]
#define S_W0   27648                   // buf stride 12288 (256 rows x 48B)
#define S_V0   52224                   // buf stride 6144  (V fp16, 128 rows)
#define S_TOTAL 64512

// ---------------------------------------------------------------------------
// k_prep: round w2 (fp32 [o][ck]) to fp16, tiled [chunk][o][ck%16]
// ---------------------------------------------------------------------------
__global__ void k_prep(const float* __restrict__ w2) {
    int i = blockIdx.x * 512 + threadIdx.x;     // 1152*512 = 589824 exact
    int o  = i / CK;
    int ck = i - o * CK;
    float v = w2[i];
    unsigned short hb;
    asm("cvt.rn.f16.f32 %0, %1;" : "=h"(hb) : "f"(v));
    int dst = ((ck >> 4) * COUT + o) * KC + (ck & 15);
    g_w2h[dst] = hb;
}

// ---------------------------------------------------------------------------
// k_off: offset-predicting 3x3 conv (18 out channels), pad=1 stride=1.
// fma-pipe bound -> packed f32x2 FFMA2 (exact fp32 semantics, 2x rate).
// ws laid out [c][k][half*10 + j] so weight pairs are 8B-aligned LDS.64.
// Per-channel accumulation order unchanged -> g_offset bit-identical.
// ---------------------------------------------------------------------------
__global__ __launch_bounds__(256) void k_off(const float* __restrict__ x,
                                             const float* __restrict__ w1) {
    __shared__ float xs[8][4][66];
    __shared__ float ws[8][9][20];   // [c][k][half*10+j], j<9 used

    int n  = blockIdx.x >> 5;
    int y0 = (blockIdx.x & 31) * 2;
    int tid = threadIdx.x;
    int p    = tid >> 1;
    int half = tid & 1;
    int r   = p >> 6;
    int col = p & 63;
    int hofs = half * 10;

    unsigned long long acc2[4];
    float acc8 = 0.f;
#pragma unroll
    for (int q = 0; q < 4; q++) acc2[q] = 0ull;

    for (int cb = 0; cb < CIN; cb += 8) {
        for (int l = tid; l < 8 * 4 * 66; l += 256) {
            int c  = l / 264;
            int rem = l - c * 264;
            int y  = rem / 66;
            int xc = rem - y * 66;
            int gy = y0 - 1 + y;
            int gx = xc - 1;
            float v = 0.f;
            if ((unsigned)gy < 64u && (unsigned)gx < 64u)
                v = x[((n * CIN + cb + c) * 64 + gy) * 64 + gx];
            xs[c][y][xc] = v;
        }
        // weights: o 0..17 -> [c][k][(o/9)*10 + o%9]
        for (int l = tid; l < 8 * 9 * 18; l += 256) {
            int o = l % 18;
            int k = (l / 18) % 9;
            int c = l / 162;
            int hh = o / 9, jj = o - hh * 9;
            ws[c][k][hh * 10 + jj] = w1[(o * CIN + cb + c) * 9 + k];
        }
        __syncthreads();

#pragma unroll
        for (int c = 0; c < 8; c++) {
            float xv[9];
#pragma unroll
            for (int ky = 0; ky < 3; ky++)
#pragma unroll
                for (int kx = 0; kx < 3; kx++)
                    xv[ky * 3 + kx] = xs[c][r + ky][col + kx];
#pragma unroll
            for (int k = 0; k < 9; k++) {
                float v = xv[k];
                unsigned long long vp;
                asm("mov.b64 %0, {%1, %1};" : "=l"(vp) : "f"(v));
                const float* wr = &ws[c][k][hofs];
#pragma unroll
                for (int q = 0; q < 4; q++) {
                    float2 wp2 = *(const float2*)(wr + q * 2);   // aligned
                    unsigned long long wp;
                    asm("mov.b64 %0, {%1, %2};" : "=l"(wp) : "f"(wp2.x), "f"(wp2.y));
                    asm("fma.rn.f32x2 %0, %1, %2, %0;"
                        : "+l"(acc2[q]) : "l"(wp), "l"(vp));
                }
                acc8 += wr[8] * v;
            }
        }
        __syncthreads();
    }

    int hw = (y0 + r) * 64 + col;
    int obase = half * 9;
#pragma unroll
    for (int q = 0; q < 4; q++) {
        float lo, hi;
        asm("mov.b64 {%0, %1}, %2;" : "=f"(lo), "=f"(hi) : "l"(acc2[q]));
        g_offset[(n * 18 + obase + q * 2)     * HW + hw] = lo;
        g_offset[(n * 18 + obase + q * 2 + 1) * HW + hw] = hi;
    }
    g_offset[(n * 18 + obase + 8) * HW + hw] = acc8;
}

// ---------------------------------------------------------------------------
// HMMA wrapper
// ---------------------------------------------------------------------------
__device__ __forceinline__ void mma16816f(float* c, const uint32_t* a,
                                          const uint32_t* b) {
    asm volatile(
        "mma.sync.aligned.m16n8k16.row.col.f32.f16.f16.f32 "
        "{%0,%1,%2,%3}, {%4,%5,%6,%7}, {%8,%9}, {%0,%1,%2,%3};"
        : "+f"(c[0]), "+f"(c[1]), "+f"(c[2]), "+f"(c[3])
        : "r"(a[0]), "r"(a[1]), "r"(a[2]), "r"(a[3]), "r"(b[0]), "r"(b[1]));
}

// ---------------------------------------------------------------------------
// k_main: register-pipelined gather -> single-pass fp16 mma.sync GEMM
// Block: 512 threads (16 warps, 4m x 4n), tile 256o x 128p, K-chunk 16,
// double-buffered SMEM, ONE __syncthreads per chunk (post-MMA barrier
// removed: store(cb+2)->cur is ordered after MMA(cb)->cur via syncA(cb+1)).
// Grid: 8 n * 32 ptiles = 256 blocks.  [R12 structure; halo reverted]
// ---------------------------------------------------------------------------
__global__ __launch_bounds__(512, 1) void k_main(const float* __restrict__ x,
                                                 const float* __restrict__ b2,
                                                 float* __restrict__ out) {
    extern __shared__ __align__(16) char smem[];
    int tid = threadIdx.x;
    int wid = tid >> 5;
    int lane = tid & 31;
    int g  = lane >> 2;
    int t2 = lane & 3;

    int n     = blockIdx.x >> 5;
    int pbase = (blockIdx.x & 31) * 128;

    int o_base = (wid & 3) * 64;
    int p_base = (wid >> 2) * 32;
    int pg = tid & 127;          // gather position
    int jg = tid >> 7;           // gather ck-group (0..3), 4 ck each

    // ---- bilinear table: 9 taps x 128 positions ----
    for (int t = tid; t < 1152; t += 512) {
        int tap = t >> 7;
        int p   = t & 127;
        int hw  = pbase + p;
        int h   = hw >> 6;
        int w   = hw & 63;
        float dy = g_offset[(n * 18 + 2 * tap)     * HW + hw];
        float dx = g_offset[(n * 18 + 2 * tap + 1) * HW + hw];
        float py = (float)(h - 1 + tap / 3) + dy;
        float px = (float)(w - 1 + tap % 3) + dx;
        float fy = floorf(py), fx = floorf(px);
        float wy = py - fy, wx = px - fx;
        int y0 = (int)fy, x0 = (int)fx;
        float vy0 = ((unsigned)y0       < 64u) ? 1.f : 0.f;
        float vy1 = ((unsigned)(y0 + 1) < 64u) ? 1.f : 0.f;
        float vx0 = ((unsigned)x0       < 64u) ? 1.f : 0.f;
        float vx1 = ((unsigned)(x0 + 1) < 64u) ? 1.f : 0.f;
        float wy0 = (1.f - wy) * vy0, wy1 = wy * vy1;
        float wx0 = (1.f - wx) * vx0, wx1 = wx * vx1;
        int y0c = min(max(y0, 0), 63), y1c = min(max(y0 + 1, 0), 63);
        int x0c = min(max(x0, 0), 63), x1c = min(max(x0 + 1, 0), 63);
        int a00 = (y0c << 6) + x0c;
        int dxo = x1c - x0c;
        int dyo = (y1c - y0c) << 6;
        *(int2*)(smem + S_TABA + t * 8)    = make_int2(a00, dxo | (dyo << 16));
        *(float4*)(smem + S_TABW + t * 16) = make_float4(wy0 * wx0, wy0 * wx1,
                                                         wy1 * wx0, wy1 * wx1);
    }

    float acc[4][4][4];
#pragma unroll
    for (int mt = 0; mt < 4; mt++)
#pragma unroll
        for (int nt = 0; nt < 4; nt++)
#pragma unroll
            for (int j = 0; j < 4; j++) acc[mt][nt][j] = 0.f;

    const float* xn = x + ((size_t)n << 20);

    int wrow = tid >> 1;
    int wseg = tid & 1;
    const uint4* wsrch = (const uint4*)(g_w2h);

    __syncthreads();

    float raw[16];
    uint4 wregh;

    // ---- prologue: fetch chunk 0 into registers ----
    {
        int ck0 = jg * 4;
        int c = ck0 / 9, tap = ck0 - c * 9;
#pragma unroll
        for (int kk = 0; kk < 4; kk++) {
            int t = (tap << 7) + pg;
            int2 ia = *(const int2*)(smem + S_TABA + t * 8);
            const float* xp = xn + (c << 12);
            int a00 = ia.x, dxo = ia.y & 0xFFFF, dyo = ia.y >> 16;
            raw[kk * 4 + 0] = __ldg(xp + a00);
            raw[kk * 4 + 1] = __ldg(xp + a00 + dxo);
            raw[kk * 4 + 2] = __ldg(xp + a00 + dyo);
            raw[kk * 4 + 3] = __ldg(xp + a00 + dyo + dxo);
            if (++tap == 9) { tap = 0; c++; }
        }
        wregh = wsrch[(0 * COUT + wrow) * 2 + wseg];
    }

    for (int cb = 0; cb < NCH; cb++) {
        int cur = cb & 1;

        // ---- store prefetched chunk cb into buf cur ----
        {
            int ck0 = cb * KC + jg * 4;
            int tap = ck0 % 9;
            unsigned vb2[2];
#pragma unroll
            for (int kk = 0; kk < 4; kk++) {
                int t = (tap << 7) + pg;
                float4 wt = *(const float4*)(smem + S_TABW + t * 16);
                float v = wt.x * raw[kk * 4 + 0] + wt.y * raw[kk * 4 + 1]
                        + wt.z * raw[kk * 4 + 2] + wt.w * raw[kk * 4 + 3];
                unsigned short hv;
                asm("cvt.rn.f16.f32 %0, %1;" : "=h"(hv) : "f"(v));
                if (kk & 1) vb2[kk >> 1] |= ((unsigned)hv) << 16;
                else        vb2[kk >> 1]  = hv;
                if (++tap == 9) tap = 0;
            }
            *(uint2*)(smem + S_V0 + cur * 6144 + pg * WSTR + jg * 8)
                = make_uint2(vb2[0], vb2[1]);
            *(uint4*)(smem + S_W0 + cur * 12288 + wrow * WSTR + wseg * 16)
                = wregh;
        }
        __syncthreads();   // the ONLY barrier per chunk

        // ---- issue prefetch for chunk cb+1 (LDGs fly under the MMAs) ----
        if (cb + 1 < NCH) {
            int ck0 = (cb + 1) * KC + jg * 4;
            int c = ck0 / 9, tap = ck0 - c * 9;
#pragma unroll
            for (int kk = 0; kk < 4; kk++) {
                int t = (tap << 7) + pg;
                int2 ia = *(const int2*)(smem + S_TABA + t * 8);
                const float* xp = xn + (c << 12);
                int a00 = ia.x, dxo = ia.y & 0xFFFF, dyo = ia.y >> 16;
                raw[kk * 4 + 0] = __ldg(xp + a00);
                raw[kk * 4 + 1] = __ldg(xp + a00 + dxo);
                raw[kk * 4 + 2] = __ldg(xp + a00 + dyo);
                raw[kk * 4 + 3] = __ldg(xp + a00 + dyo + dxo);
                if (++tap == 9) { tap = 0; c++; }
            }
            wregh = wsrch[((cb + 1) * COUT + wrow) * 2 + wseg];
        }

        // ---- MMA on buf cur: single fp16 pass ----
        const char* wh = smem + S_W0 + cur * 12288;
        const char* vv = smem + S_V0 + cur * 6144;

        uint32_t b[4][2];
#pragma unroll
        for (int nt = 0; nt < 4; nt++) {
            const char* rp = vv + (p_base + nt * 8 + g) * WSTR + t2 * 4;
            b[nt][0] = *(const uint32_t*)(rp);
            b[nt][1] = *(const uint32_t*)(rp + 16);
        }
#pragma unroll
        for (int mt = 0; mt < 4; mt++) {
            int ro = (o_base + mt * 16 + g) * WSTR + t2 * 4;
            uint32_t ah[4];
            ah[0] = *(const uint32_t*)(wh + ro);
            ah[1] = *(const uint32_t*)(wh + ro + 8 * WSTR);
            ah[2] = *(const uint32_t*)(wh + ro + 16);
            ah[3] = *(const uint32_t*)(wh + ro + 8 * WSTR + 16);
#pragma unroll
            for (int nt = 0; nt < 4; nt++)
                mma16816f(acc[mt][nt], ah, b[nt]);
        }
        // no post-MMA barrier: next store targets the other buffer, and the
        // following syncA orders it; buffer reuse (cb+2) is transitively
        // ordered after these MMA reads.
    }

    // ---- epilogue: bias + float2 stores ----
#pragma unroll
    for (int mt = 0; mt < 4; mt++) {
        int o0 = o_base + mt * 16 + g;
        float bias0 = b2[o0];
        float bias1 = b2[o0 + 8];
        float* row0 = out + (size_t)(n * COUT + o0) * HW + pbase;
        float* row1 = row0 + 8 * HW;
#pragma unroll
        for (int nt = 0; nt < 4; nt++) {
            int p = p_base + nt * 8 + t2 * 2;
            *(float2*)(row0 + p) = make_float2(acc[mt][nt][0] + bias0,
                                               acc[mt][nt][1] + bias0);
            *(float2*)(row1 + p) = make_float2(acc[mt][nt][2] + bias1,
                                               acc[mt][nt][3] + bias1);
        }
    }
}

// ---------------------------------------------------------------------------
extern "C" void kernel_launch(void* const* d_in, const int* in_sizes, int n_in,
                              void* d_out, int out_size) {
    const float* x  = (const float*)d_in[0];
    const float* w1 = (const float*)d_in[1];
    const float* w2 = (const float*)d_in[2];
    const float* b2 = (const float*)d_in[3];
    float* out = (float*)d_out;

    cudaFuncSetAttribute(k_main, cudaFuncAttributeMaxDynamicSharedMemorySize,
                         S_TOTAL);

    k_prep<<<1152, 512>>>(w2);
    k_off<<<NB * 32, 256>>>(x, w1);
    k_main<<<NB * 32, 512, S_TOTAL>>>(x, b2, out);
}